// round 13
// baseline (speedup 1.0000x reference)
#include <cuda_runtime.h>
#include <cuda_fp16.h>
#include <cstdint>

#define NN 100000
#define EE 1600000
#define HH 128
#define GG 512
#define BN_EPS 1e-5f
#define SCAN_B 1024
#define NB ((NN + SCAN_B - 1) / SCAN_B)   // 98 scan blocks
#define NTILES 782                         // ceil(NN/128)

// ---------------- scratch (device globals: no allocation allowed) -----------
__device__ __half g_t[(size_t)NN * HH];    // ping buffer (fp16)
__device__ __half g_h[(size_t)NN * HH];    // agg output buffer (fp16)
__device__ __half g_t2[(size_t)NN * HH];   // second ping buffer (fp16)
__device__ __half g_Wh[3 * HH * HH];       // BN-folded fp16 weights
__device__ float  g_beta[3 * HH];          // BN-folded shifts
__device__ float  g_dinv[NN];
__device__ int    g_deg[NN];
__device__ int    g_rowptr[NN + 1];
__device__ int    g_cursor[NN];
__device__ int    g_col[EE];
__device__ float  g_gsum[GG];
__device__ int    g_gcnt[GG];
__device__ int    g_part[NB];

__device__ __forceinline__ uint32_t s2u(const void* p) {
    return (uint32_t)__cvta_generic_to_shared(p);
}

// ---------------- preprocessing kernels ------------------------------------
__global__ void k_zero() {
    int i = blockIdx.x * blockDim.x + threadIdx.x;
    if (i < NN) g_deg[i] = 0;
    if (i < GG) { g_gsum[i] = 0.0f; g_gcnt[i] = 0; }
}

__global__ void k_hist(const int* __restrict__ ei, const int* __restrict__ batch) {
    int e = blockIdx.x * blockDim.x + threadIdx.x;
    if (e < EE) atomicAdd(&g_deg[ei[EE + e]], 1);
    if (e < NN) atomicAdd(&g_gcnt[batch[e]], 1);
}

__global__ void k_scan_local() {
    __shared__ int sh[SCAN_B];
    int tx = threadIdx.x;
    int i = blockIdx.x * SCAN_B + tx;
    int v = (i < NN) ? g_deg[i] : 0;
    if (i < NN) g_dinv[i] = rsqrtf((float)(v + 1));   // fused dinv (+1 self-loop)
    sh[tx] = v;
    __syncthreads();
    for (int off = 1; off < SCAN_B; off <<= 1) {
        int t = (tx >= off) ? sh[tx - off] : 0;
        __syncthreads();
        sh[tx] += t;
        __syncthreads();
    }
    if (i < NN) g_rowptr[i] = sh[tx] - v;        // exclusive
    if (tx == SCAN_B - 1) g_part[blockIdx.x] = sh[tx];
}

__global__ void k_scan_part() {
    __shared__ int sh[128];
    int tx = threadIdx.x;
    int v = (tx < NB) ? g_part[tx] : 0;
    sh[tx] = v;
    __syncthreads();
    for (int off = 1; off < 128; off <<= 1) {
        int t = (tx >= off) ? sh[tx - off] : 0;
        __syncthreads();
        sh[tx] += t;
        __syncthreads();
    }
    if (tx < NB) g_part[tx] = sh[tx] - v;        // exclusive block offsets
}

__global__ void k_scan_add() {
    int i = blockIdx.x * blockDim.x + threadIdx.x;
    if (i < NN) {
        int v = g_rowptr[i] + g_part[i >> 10];
        g_rowptr[i] = v;
        g_cursor[i] = v;
    }
    if (i == 0) g_rowptr[NN] = EE;
}

__global__ void k_fill(const int* __restrict__ ei) {
    int e = blockIdx.x * blockDim.x + threadIdx.x;
    if (e < EE) {
        int src = ei[e];
        int dst = ei[EE + e];
        int p = atomicAdd(&g_cursor[dst], 1);
        g_col[p] = src;
    }
}

// Fold BN scale into W columns (fp16) for all 3 layers, compute folded shifts.
__global__ void k_prep_w(const float* __restrict__ W1v, const float* __restrict__ W2v,
                         const float* __restrict__ W3v,
                         const float* __restrict__ b1v, const float* __restrict__ b2v,
                         const float* __restrict__ b3v,
                         const float* __restrict__ ga1, const float* __restrict__ ga2,
                         const float* __restrict__ ga3,
                         const float* __restrict__ be1, const float* __restrict__ be2,
                         const float* __restrict__ be3,
                         const float* __restrict__ m1v, const float* __restrict__ m2v,
                         const float* __restrict__ m3v,
                         const float* __restrict__ v1v, const float* __restrict__ v2v,
                         const float* __restrict__ v3v) {
    int layer = blockIdx.y;
    const float* W  = layer == 0 ? W1v : layer == 1 ? W2v : W3v;
    const float* b  = layer == 0 ? b1v : layer == 1 ? b2v : b3v;
    const float* ga = layer == 0 ? ga1 : layer == 1 ? ga2 : ga3;
    const float* be = layer == 0 ? be1 : layer == 1 ? be2 : be3;
    const float* m  = layer == 0 ? m1v : layer == 1 ? m2v : m3v;
    const float* v  = layer == 0 ? v1v : layer == 1 ? v2v : v3v;
    int idx = blockIdx.x * blockDim.x + threadIdx.x;
    if (idx < HH * HH) {
        int n = idx & (HH - 1);
        float alpha = ga[n] * rsqrtf(v[n] + BN_EPS);
        g_Wh[layer * HH * HH + idx] = __float2half(W[idx] * alpha);
    }
    if (idx < HH) {
        float alpha = ga[idx] * rsqrtf(v[idx] + BN_EPS);
        g_beta[layer * HH + idx] = (b[idx] - m[idx]) * alpha + be[idx];
    }
}

// ---------------- fp16 tensor-core GEMM + dinv prescale epilogue -----------
// Y[i,:] = dinv[i] * (X[i,:] @ W).  tile0: chunk offset in 128-row tiles.
template <bool F32IN>
__global__ void __launch_bounds__(256) k_gemm_tc(const void* __restrict__ Xv,
                                                 const __half* __restrict__ W,
                                                 __half* __restrict__ Y,
                                                 int tile0) {
    extern __shared__ __half sh[];
    __half* As = sh;               // 128 x 136 (272 B pitch)
    __half* Ws = sh + 128 * 136;   // 128 x 136 (row = k, cols = n)

    int tid = threadIdx.x;
    int row0 = (tile0 + blockIdx.x) * 128;

    if (F32IN) {
        const uint4* Wg = (const uint4*)W;
#pragma unroll
        for (int i = 0; i < 8; i++) {
            int idx = i * 256 + tid;
            int r = idx >> 4, c = (idx & 15) * 8;
            *(uint4*)&Ws[r * 136 + c] = Wg[idx];
        }
        const float4* Xg = (const float4*)Xv;
#pragma unroll
        for (int i = 0; i < 16; i++) {
            int idx = i * 256 + tid;
            int r = idx >> 5, c = (idx & 31) * 4;
            float4 v = make_float4(0.f, 0.f, 0.f, 0.f);
            if (row0 + r < NN) v = Xg[(size_t)(row0 + r) * 32 + (idx & 31)];
            *(__half2*)&As[r * 136 + c]     = __floats2half2_rn(v.x, v.y);
            *(__half2*)&As[r * 136 + c + 2] = __floats2half2_rn(v.z, v.w);
        }
        __syncthreads();
    } else {
        const char* Ag = (const char*)Xv;     // 256 B per row (k bytes)
        const char* Wg = (const char*)W;      // 256 B per row (row = k, bytes = n)
#pragma unroll
        for (int h = 0; h < 2; h++) {
#pragma unroll
            for (int i = 0; i < 4; i++) {     // A: 1024 chunks
                int idx = i * 256 + tid;
                int r = idx >> 3, ch = idx & 7;
                uint32_t saddr = s2u(&As[0]) + r * 272 + h * 128 + ch * 16;
                const char* gaddr = Ag + (size_t)(row0 + r) * 256 + h * 128 + ch * 16;
                int sz = (row0 + r < NN) ? 16 : 0;
                asm volatile("cp.async.cg.shared.global [%0], [%1], 16, %2;"
                             :: "r"(saddr), "l"(gaddr), "r"(sz));
            }
#pragma unroll
            for (int i = 0; i < 4; i++) {     // W: 64 rows x 16 chunks
                int idx = i * 256 + tid;
                int r = h * 64 + (idx >> 4);
                int ch = idx & 15;
                uint32_t saddr = s2u(&Ws[0]) + r * 272 + ch * 16;
                const char* gaddr = Wg + (size_t)r * 256 + ch * 16;
                asm volatile("cp.async.cg.shared.global [%0], [%1], 16;"
                             :: "r"(saddr), "l"(gaddr));
            }
            asm volatile("cp.async.commit_group;");
        }
    }

    int wid = tid >> 5, lane = tid & 31;
    int m0 = wid * 16;

    float acc[16][4];
#pragma unroll
    for (int nt = 0; nt < 16; nt++)
#pragma unroll
        for (int c = 0; c < 4; c++) acc[nt][c] = 0.f;

#pragma unroll
    for (int h = 0; h < 2; h++) {
        if (!F32IN) {
            if (h == 0) { asm volatile("cp.async.wait_group 1;"); }
            else        { asm volatile("cp.async.wait_group 0;"); }
            __syncthreads();
        }
#pragma unroll
        for (int ksl = 0; ksl < 4; ksl++) {
            int ks = h * 4 + ksl;
            uint32_t a0, a1, a2, a3;
            uint32_t aaddr = s2u(&As[(m0 + (lane & 15)) * 136 + ks * 16 + (lane >> 4) * 8]);
            asm volatile("ldmatrix.sync.aligned.m8n8.x4.shared.b16 {%0,%1,%2,%3}, [%4];"
                         : "=r"(a0), "=r"(a1), "=r"(a2), "=r"(a3) : "r"(aaddr));
#pragma unroll
            for (int ng = 0; ng < 8; ng++) {
                uint32_t b0, b1, b2, b3;
                uint32_t baddr = s2u(&Ws[(ks * 16 + (lane & 15)) * 136 +
                                         ng * 16 + (lane >> 4) * 8]);
                asm volatile("ldmatrix.sync.aligned.m8n8.x4.trans.shared.b16 {%0,%1,%2,%3}, [%4];"
                             : "=r"(b0), "=r"(b1), "=r"(b2), "=r"(b3) : "r"(baddr));
                int nt = ng * 2;
                asm volatile(
                    "mma.sync.aligned.m16n8k16.row.col.f32.f16.f16.f32 "
                    "{%0,%1,%2,%3}, {%4,%5,%6,%7}, {%8,%9}, {%0,%1,%2,%3};"
                    : "+f"(acc[nt][0]), "+f"(acc[nt][1]), "+f"(acc[nt][2]), "+f"(acc[nt][3])
                    : "r"(a0), "r"(a1), "r"(a2), "r"(a3), "r"(b0), "r"(b1));
                asm volatile(
                    "mma.sync.aligned.m16n8k16.row.col.f32.f16.f16.f32 "
                    "{%0,%1,%2,%3}, {%4,%5,%6,%7}, {%8,%9}, {%0,%1,%2,%3};"
                    : "+f"(acc[nt + 1][0]), "+f"(acc[nt + 1][1]), "+f"(acc[nt + 1][2]), "+f"(acc[nt + 1][3])
                    : "r"(a0), "r"(a1), "r"(a2), "r"(a3), "r"(b2), "r"(b3));
            }
        }
    }

    int r0 = row0 + m0 + (lane >> 2);
    int cb = (lane & 3) * 2;
    float d0, d1;
    if (F32IN) {
        d0 = (r0 < NN) ? rsqrtf((float)(g_deg[r0] + 1)) : 0.f;
        d1 = (r0 + 8 < NN) ? rsqrtf((float)(g_deg[r0 + 8] + 1)) : 0.f;
    } else {
        d0 = (r0 < NN) ? g_dinv[r0] : 0.f;
        d1 = (r0 + 8 < NN) ? g_dinv[r0 + 8] : 0.f;
    }
#pragma unroll
    for (int nt = 0; nt < 16; nt++) {
        if (r0 < NN)
            *(__half2*)&Y[(size_t)r0 * 128 + nt * 8 + cb] =
                __floats2half2_rn(acc[nt][0] * d0, acc[nt][1] * d0);
        if (r0 + 8 < NN)
            *(__half2*)&Y[(size_t)(r0 + 8) * 128 + nt * 8 + cb] =
                __floats2half2_rn(acc[nt][2] * d1, acc[nt][3] * d1);
    }
}

// ---------------- aggregation + folded-BN + ReLU (2 nodes per warp) --------
// Tin: gather source. node0: chunk offset. t' pre-scaled by dinv[src].
template <bool FINAL>
__global__ void __launch_bounds__(256) k_agg16(const __half* __restrict__ Tin,
                                               const float* __restrict__ beta,
                                               const float* __restrict__ Wl,
                                               const int* __restrict__ batch,
                                               int node0) {
    int warp = (blockIdx.x * blockDim.x + threadIdx.x) >> 5;
    int lane = threadIdx.x & 31;
    int half = lane >> 4;
    int sub = lane & 15;
    int node = node0 + warp * 2 + half;
    if (node >= NN) return;

    const uint4* T = (const uint4*)Tin;   // 16 x uint4 (8 halves) per row
    float di = g_dinv[node];

    float acc[8];
    {
        uint4 u = T[(size_t)node * 16 + sub];   // self term t'[i]
        const __half2* p = (const __half2*)&u;
#pragma unroll
        for (int q = 0; q < 4; q++) {
            float2 f = __half22float2(p[q]);
            acc[q * 2] = f.x; acc[q * 2 + 1] = f.y;
        }
    }

    int e = g_rowptr[node];
    int e1 = g_rowptr[node + 1];

    for (; e + 8 <= e1; e += 8) {
        int s[8];
        uint4 v[8];
#pragma unroll
        for (int j = 0; j < 8; j++) s[j] = __ldg(&g_col[e + j]);
#pragma unroll
        for (int j = 0; j < 8; j++) v[j] = T[(size_t)s[j] * 16 + sub];
#pragma unroll
        for (int j = 0; j < 8; j++) {
            const __half2* p = (const __half2*)&v[j];
#pragma unroll
            for (int q = 0; q < 4; q++) {
                float2 f = __half22float2(p[q]);
                acc[q * 2] += f.x; acc[q * 2 + 1] += f.y;
            }
        }
    }
    for (; e + 4 <= e1; e += 4) {
        int s[4];
        uint4 v[4];
#pragma unroll
        for (int j = 0; j < 4; j++) s[j] = __ldg(&g_col[e + j]);
#pragma unroll
        for (int j = 0; j < 4; j++) v[j] = T[(size_t)s[j] * 16 + sub];
#pragma unroll
        for (int j = 0; j < 4; j++) {
            const __half2* p = (const __half2*)&v[j];
#pragma unroll
            for (int q = 0; q < 4; q++) {
                float2 f = __half22float2(p[q]);
                acc[q * 2] += f.x; acc[q * 2 + 1] += f.y;
            }
        }
    }
    for (; e < e1; ++e) {
        int s = __ldg(&g_col[e]);
        uint4 v = T[(size_t)s * 16 + sub];
        const __half2* p = (const __half2*)&v;
#pragma unroll
        for (int q = 0; q < 4; q++) {
            float2 f = __half22float2(p[q]);
            acc[q * 2] += f.x; acc[q * 2 + 1] += f.y;
        }
    }

    float4 be0 = ((const float4*)beta)[sub * 2];
    float4 be1v = ((const float4*)beta)[sub * 2 + 1];
    float y[8];
    y[0] = fmaxf(0.f, fmaf(di, acc[0], be0.x));
    y[1] = fmaxf(0.f, fmaf(di, acc[1], be0.y));
    y[2] = fmaxf(0.f, fmaf(di, acc[2], be0.z));
    y[3] = fmaxf(0.f, fmaf(di, acc[3], be0.w));
    y[4] = fmaxf(0.f, fmaf(di, acc[4], be1v.x));
    y[5] = fmaxf(0.f, fmaf(di, acc[5], be1v.y));
    y[6] = fmaxf(0.f, fmaf(di, acc[6], be1v.z));
    y[7] = fmaxf(0.f, fmaf(di, acc[7], be1v.w));

    if (!FINAL) {
        uint4 o;
        __half2* p = (__half2*)&o;
        p[0] = __floats2half2_rn(y[0], y[1]);
        p[1] = __floats2half2_rn(y[2], y[3]);
        p[2] = __floats2half2_rn(y[4], y[5]);
        p[3] = __floats2half2_rn(y[6], y[7]);
        ((uint4*)g_h)[(size_t)node * 16 + sub] = o;
    } else {
        float4 wl0 = ((const float4*)Wl)[sub * 2];
        float4 wl1 = ((const float4*)Wl)[sub * 2 + 1];
        float s = y[0] * wl0.x + y[1] * wl0.y + y[2] * wl0.z + y[3] * wl0.w +
                  y[4] * wl1.x + y[5] * wl1.y + y[6] * wl1.z + y[7] * wl1.w;
        unsigned mask = half ? 0xFFFF0000u : 0x0000FFFFu;
#pragma unroll
        for (int off = 8; off > 0; off >>= 1)
            s += __shfl_xor_sync(mask, s, off);
        if (sub == 0) atomicAdd(&g_gsum[batch[node]], s);
    }
}

__global__ void k_final(float* __restrict__ out, const float* __restrict__ bl) {
    int g = blockIdx.x * blockDim.x + threadIdx.x;
    if (g < GG) out[g] = g_gsum[g] / fmaxf((float)g_gcnt[g], 1.0f) + bl[0];
}

// ---------------- host launcher --------------------------------------------
extern "C" void kernel_launch(void* const* d_in, const int* in_sizes, int n_in,
                              void* d_out, int out_size) {
    const float* x     = (const float*)d_in[0];
    const int*   ei    = (const int*)d_in[1];
    const int*   batch = (const int*)d_in[2];
    const float* W1 = (const float*)d_in[3];
    const float* b1 = (const float*)d_in[4];
    const float* g1 = (const float*)d_in[5];
    const float* be1 = (const float*)d_in[6];
    const float* m1 = (const float*)d_in[7];
    const float* v1 = (const float*)d_in[8];
    const float* W2 = (const float*)d_in[9];
    const float* b2 = (const float*)d_in[10];
    const float* g2 = (const float*)d_in[11];
    const float* be2 = (const float*)d_in[12];
    const float* m2 = (const float*)d_in[13];
    const float* v2 = (const float*)d_in[14];
    const float* W3 = (const float*)d_in[15];
    const float* b3 = (const float*)d_in[16];
    const float* g3 = (const float*)d_in[17];
    const float* be3 = (const float*)d_in[18];
    const float* m3 = (const float*)d_in[19];
    const float* v3 = (const float*)d_in[20];
    const float* Wl = (const float*)d_in[21];
    const float* bl = (const float*)d_in[22];

    __half *t, *h, *t2, *Wh;
    float *beta;
    cudaGetSymbolAddress((void**)&t, g_t);
    cudaGetSymbolAddress((void**)&h, g_h);
    cudaGetSymbolAddress((void**)&t2, g_t2);
    cudaGetSymbolAddress((void**)&Wh, g_Wh);
    cudaGetSymbolAddress((void**)&beta, g_beta);

    const int GEMM_SMEM = 2 * 128 * 136 * (int)sizeof(__half);   // 69632
    cudaFuncSetAttribute(k_gemm_tc<true>,  cudaFuncAttributeMaxDynamicSharedMemorySize, GEMM_SMEM);
    cudaFuncSetAttribute(k_gemm_tc<false>, cudaFuncAttributeMaxDynamicSharedMemorySize, GEMM_SMEM);

    static cudaStream_t s1 = nullptr;
    static cudaEvent_t evStart = nullptr, evHist = nullptr, evG1 = nullptr;
    static cudaEvent_t evAgg[2][4], evJoin[2];
    if (s1 == nullptr) {
        cudaStreamCreateWithFlags(&s1, cudaStreamNonBlocking);
        cudaEventCreateWithFlags(&evStart, cudaEventDisableTiming);
        cudaEventCreateWithFlags(&evHist, cudaEventDisableTiming);
        cudaEventCreateWithFlags(&evG1, cudaEventDisableTiming);
        for (int b = 0; b < 2; b++) {
            cudaEventCreateWithFlags(&evJoin[b], cudaEventDisableTiming);
            for (int c = 0; c < 4; c++)
                cudaEventCreateWithFlags(&evAgg[b][c], cudaEventDisableTiming);
        }
    }

    const int TPB = 256;
    const int AGG_BLOCKS = ((NN + 1) / 2 * 32 + TPB - 1) / TPB;  // 6250

    // chunk plan (in 128-row tiles): 196+196+196+194 = 782
    const int tile0[4]  = {0, 196, 392, 588};
    const int tilesC[4] = {196, 196, 196, 194};

    // ---- fork: side stream handles weight prep (input-only dependency)
    cudaEventRecord(evStart, 0);
    cudaStreamWaitEvent(s1, evStart, 0);
    {
        dim3 grid(64, 3);
        k_prep_w<<<grid, 256, 0, s1>>>(W1, W2, W3, b1, b2, b3, g1, g2, g3,
                                       be1, be2, be3, m1, m2, m3, v1, v2, v3);
    }

    // ---- main stream: graph preprocessing
    k_zero<<<(NN + TPB - 1) / TPB, TPB>>>();
    k_hist<<<(EE + TPB - 1) / TPB, TPB>>>(ei, batch);
    cudaEventRecord(evHist, 0);                         // gemm1 needs only g_deg
    k_scan_local<<<NB, SCAN_B>>>();
    k_scan_part<<<1, 128>>>();
    k_scan_add<<<(NN + TPB) / TPB, TPB>>>();
    k_fill<<<(EE + TPB - 1) / TPB, TPB>>>(ei);

    // ---- side stream: gemm1 (needs Wh + deg), overlaps the whole scan chain
    cudaStreamWaitEvent(s1, evHist, 0);
    k_gemm_tc<true><<<NTILES, 256, GEMM_SMEM, s1>>>(x, Wh, t, 0);
    cudaEventRecord(evG1, s1);
    cudaStreamWaitEvent(0, evG1, 0);

    // ---- boundary A: agg1 (t -> h) chunk-pipelined with gemm2 (h -> t2)
    for (int c = 0; c < 4; c++) {
        k_agg16<false><<<tilesC[c] * 8, TPB>>>(t, beta, nullptr, nullptr,
                                               tile0[c] * 128);
        cudaEventRecord(evAgg[0][c], 0);
        cudaStreamWaitEvent(s1, evAgg[0][c], 0);
        k_gemm_tc<false><<<tilesC[c], 256, GEMM_SMEM, s1>>>(h, Wh + HH * HH, t2,
                                                            tile0[c]);
    }
    cudaEventRecord(evJoin[0], s1);
    cudaStreamWaitEvent(0, evJoin[0], 0);

    // ---- boundary B: agg2 (t2 -> h) chunk-pipelined with gemm3 (h -> t)
    for (int c = 0; c < 4; c++) {
        k_agg16<false><<<tilesC[c] * 8, TPB>>>(t2, beta + HH, nullptr, nullptr,
                                               tile0[c] * 128);
        cudaEventRecord(evAgg[1][c], 0);
        cudaStreamWaitEvent(s1, evAgg[1][c], 0);
        k_gemm_tc<false><<<tilesC[c], 256, GEMM_SMEM, s1>>>(h, Wh + 2 * HH * HH, t,
                                                            tile0[c]);
    }
    cudaEventRecord(evJoin[1], s1);
    cudaStreamWaitEvent(0, evJoin[1], 0);

    // ---- layer-3 agg + mean-pool + linear head (reads t)
    k_agg16<true><<<AGG_BLOCKS, TPB>>>(t, beta + 2 * HH, Wl, batch, 0);

    k_final<<<(GG + TPB - 1) / TPB, TPB>>>((float*)d_out, bl);
}

// round 14
// speedup vs baseline: 1.1686x; 1.1686x over previous
#include <cuda_runtime.h>
#include <cuda_fp16.h>
#include <cstdint>

#define NN 100000
#define EE 1600000
#define HH 128
#define GG 512
#define BN_EPS 1e-5f
#define SCAN_B 1024
#define NB ((NN + SCAN_B - 1) / SCAN_B)   // 98 scan blocks

// ---------------- scratch (device globals: no allocation allowed) -----------
__device__ __half g_t[(size_t)NN * HH];   // GEMM output t' = dinv .* (h @ W') (fp16)
__device__ __half g_h[(size_t)NN * HH];   // activated hidden (fp16)
__device__ __half g_Wh[3 * HH * HH];      // BN-folded fp16 weights
__device__ float  g_beta[3 * HH];         // BN-folded shifts
__device__ float  g_dinv[NN];
__device__ int    g_deg[NN];
__device__ int    g_rowptr[NN + 1];
__device__ int    g_cursor[NN];
__device__ int    g_col[EE];
__device__ float  g_gsum[GG];
__device__ int    g_gcnt[GG];
__device__ int    g_part[NB];

__device__ __forceinline__ uint32_t s2u(const void* p) {
    return (uint32_t)__cvta_generic_to_shared(p);
}

// ---------------- preprocessing kernels ------------------------------------
__global__ void k_zero() {
    int i = blockIdx.x * blockDim.x + threadIdx.x;
    if (i < NN) g_deg[i] = 0;
    if (i < GG) { g_gsum[i] = 0.0f; g_gcnt[i] = 0; }
}

// degree histogram over dst (4 edges/thread, int4) + per-graph node counts
__global__ void k_hist(const int* __restrict__ ei, const int* __restrict__ batch) {
    int i = blockIdx.x * blockDim.x + threadIdx.x;
    if (i < EE / 4) {
        int4 d = ((const int4*)(ei + EE))[i];
        atomicAdd(&g_deg[d.x], 1);
        atomicAdd(&g_deg[d.y], 1);
        atomicAdd(&g_deg[d.z], 1);
        atomicAdd(&g_deg[d.w], 1);
    }
    if (i < NN / 4) {
        int4 b = ((const int4*)batch)[i];
        atomicAdd(&g_gcnt[b.x], 1);
        atomicAdd(&g_gcnt[b.y], 1);
        atomicAdd(&g_gcnt[b.z], 1);
        atomicAdd(&g_gcnt[b.w], 1);
    }
}

__global__ void k_scan_local() {
    __shared__ int sh[SCAN_B];
    int tx = threadIdx.x;
    int i = blockIdx.x * SCAN_B + tx;
    int v = (i < NN) ? g_deg[i] : 0;
    if (i < NN) g_dinv[i] = rsqrtf((float)(v + 1));   // fused dinv (+1 self-loop)
    sh[tx] = v;
    __syncthreads();
    for (int off = 1; off < SCAN_B; off <<= 1) {
        int t = (tx >= off) ? sh[tx - off] : 0;
        __syncthreads();
        sh[tx] += t;
        __syncthreads();
    }
    if (i < NN) g_rowptr[i] = sh[tx] - v;        // exclusive
    if (tx == SCAN_B - 1) g_part[blockIdx.x] = sh[tx];
}

__global__ void k_scan_part() {
    __shared__ int sh[128];
    int tx = threadIdx.x;
    int v = (tx < NB) ? g_part[tx] : 0;
    sh[tx] = v;
    __syncthreads();
    for (int off = 1; off < 128; off <<= 1) {
        int t = (tx >= off) ? sh[tx - off] : 0;
        __syncthreads();
        sh[tx] += t;
        __syncthreads();
    }
    if (tx < NB) g_part[tx] = sh[tx] - v;        // exclusive block offsets
}

__global__ void k_scan_add() {
    int i = blockIdx.x * blockDim.x + threadIdx.x;
    if (i < NN) {
        int v = g_rowptr[i] + g_part[i >> 10];
        g_rowptr[i] = v;
        g_cursor[i] = v;
    }
    if (i == 0) g_rowptr[NN] = EE;
}

__global__ void k_fill(const int* __restrict__ ei) {
    int e = blockIdx.x * blockDim.x + threadIdx.x;
    if (e < EE) {
        int src = ei[e];
        int dst = ei[EE + e];
        int p = atomicAdd(&g_cursor[dst], 1);
        g_col[p] = src;
    }
}

// Fold BN scale into W columns (fp16) for all 3 layers, compute folded shifts.
__global__ void k_prep_w(const float* __restrict__ W1v, const float* __restrict__ W2v,
                         const float* __restrict__ W3v,
                         const float* __restrict__ b1v, const float* __restrict__ b2v,
                         const float* __restrict__ b3v,
                         const float* __restrict__ ga1, const float* __restrict__ ga2,
                         const float* __restrict__ ga3,
                         const float* __restrict__ be1, const float* __restrict__ be2,
                         const float* __restrict__ be3,
                         const float* __restrict__ m1v, const float* __restrict__ m2v,
                         const float* __restrict__ m3v,
                         const float* __restrict__ v1v, const float* __restrict__ v2v,
                         const float* __restrict__ v3v) {
    int layer = blockIdx.y;
    const float* W  = layer == 0 ? W1v : layer == 1 ? W2v : W3v;
    const float* b  = layer == 0 ? b1v : layer == 1 ? b2v : b3v;
    const float* ga = layer == 0 ? ga1 : layer == 1 ? ga2 : ga3;
    const float* be = layer == 0 ? be1 : layer == 1 ? be2 : be3;
    const float* m  = layer == 0 ? m1v : layer == 1 ? m2v : m3v;
    const float* v  = layer == 0 ? v1v : layer == 1 ? v2v : v3v;
    int idx = blockIdx.x * blockDim.x + threadIdx.x;
    if (idx < HH * HH) {
        int n = idx & (HH - 1);
        float alpha = ga[n] * rsqrtf(v[n] + BN_EPS);
        g_Wh[layer * HH * HH + idx] = __float2half(W[idx] * alpha);
    }
    if (idx < HH) {
        float alpha = ga[idx] * rsqrtf(v[idx] + BN_EPS);
        g_beta[layer * HH + idx] = (b[idx] - m[idx]) * alpha + be[idx];
    }
}

// ---------------- fp16 tensor-core GEMM + dinv prescale epilogue -----------
// Y[i,:] = dinv[i] * (X[i,:] @ W).
// F32IN (layer 1): bulk sync loads (with f32->f16 convert); computes dinv
// directly from g_deg so it only depends on k_hist (overlaps the scan chain).
// !F32IN: cp.async 2-stage K-split; reads g_dinv.
template <bool F32IN>
__global__ void __launch_bounds__(256) k_gemm_tc(const void* __restrict__ Xv,
                                                 const __half* __restrict__ W,
                                                 __half* __restrict__ Y) {
    extern __shared__ __half sh[];
    __half* As = sh;               // 128 x 136 (272 B pitch)
    __half* Ws = sh + 128 * 136;   // 128 x 136 (row = k, cols = n)

    int tid = threadIdx.x;
    int row0 = blockIdx.x * 128;

    if (F32IN) {
        const uint4* Wg = (const uint4*)W;
#pragma unroll
        for (int i = 0; i < 8; i++) {
            int idx = i * 256 + tid;
            int r = idx >> 4, c = (idx & 15) * 8;
            *(uint4*)&Ws[r * 136 + c] = Wg[idx];
        }
        const float4* Xg = (const float4*)Xv;
#pragma unroll
        for (int i = 0; i < 16; i++) {
            int idx = i * 256 + tid;
            int r = idx >> 5, c = (idx & 31) * 4;
            float4 v = make_float4(0.f, 0.f, 0.f, 0.f);
            if (row0 + r < NN) v = Xg[(size_t)(row0 + r) * 32 + (idx & 31)];
            *(__half2*)&As[r * 136 + c]     = __floats2half2_rn(v.x, v.y);
            *(__half2*)&As[r * 136 + c + 2] = __floats2half2_rn(v.z, v.w);
        }
        __syncthreads();
    } else {
        const char* Ag = (const char*)Xv;     // 256 B per row (k bytes)
        const char* Wg = (const char*)W;      // 256 B per row (row = k, bytes = n)
#pragma unroll
        for (int h = 0; h < 2; h++) {
#pragma unroll
            for (int i = 0; i < 4; i++) {     // A: 1024 chunks
                int idx = i * 256 + tid;
                int r = idx >> 3, ch = idx & 7;
                uint32_t saddr = s2u(&As[0]) + r * 272 + h * 128 + ch * 16;
                const char* gaddr = Ag + (size_t)(row0 + r) * 256 + h * 128 + ch * 16;
                int sz = (row0 + r < NN) ? 16 : 0;
                asm volatile("cp.async.cg.shared.global [%0], [%1], 16, %2;"
                             :: "r"(saddr), "l"(gaddr), "r"(sz));
            }
#pragma unroll
            for (int i = 0; i < 4; i++) {     // W: 64 rows x 16 chunks
                int idx = i * 256 + tid;
                int r = h * 64 + (idx >> 4);
                int ch = idx & 15;
                uint32_t saddr = s2u(&Ws[0]) + r * 272 + ch * 16;
                const char* gaddr = Wg + (size_t)r * 256 + ch * 16;
                asm volatile("cp.async.cg.shared.global [%0], [%1], 16;"
                             :: "r"(saddr), "l"(gaddr));
            }
            asm volatile("cp.async.commit_group;");
        }
    }

    int wid = tid >> 5, lane = tid & 31;
    int m0 = wid * 16;

    float acc[16][4];
#pragma unroll
    for (int nt = 0; nt < 16; nt++)
#pragma unroll
        for (int c = 0; c < 4; c++) acc[nt][c] = 0.f;

#pragma unroll
    for (int h = 0; h < 2; h++) {
        if (!F32IN) {
            if (h == 0) { asm volatile("cp.async.wait_group 1;"); }
            else        { asm volatile("cp.async.wait_group 0;"); }
            __syncthreads();
        }
#pragma unroll
        for (int ksl = 0; ksl < 4; ksl++) {
            int ks = h * 4 + ksl;
            uint32_t a0, a1, a2, a3;
            uint32_t aaddr = s2u(&As[(m0 + (lane & 15)) * 136 + ks * 16 + (lane >> 4) * 8]);
            asm volatile("ldmatrix.sync.aligned.m8n8.x4.shared.b16 {%0,%1,%2,%3}, [%4];"
                         : "=r"(a0), "=r"(a1), "=r"(a2), "=r"(a3) : "r"(aaddr));
#pragma unroll
            for (int ng = 0; ng < 8; ng++) {
                uint32_t b0, b1, b2, b3;
                uint32_t baddr = s2u(&Ws[(ks * 16 + (lane & 15)) * 136 +
                                         ng * 16 + (lane >> 4) * 8]);
                asm volatile("ldmatrix.sync.aligned.m8n8.x4.trans.shared.b16 {%0,%1,%2,%3}, [%4];"
                             : "=r"(b0), "=r"(b1), "=r"(b2), "=r"(b3) : "r"(baddr));
                int nt = ng * 2;
                asm volatile(
                    "mma.sync.aligned.m16n8k16.row.col.f32.f16.f16.f32 "
                    "{%0,%1,%2,%3}, {%4,%5,%6,%7}, {%8,%9}, {%0,%1,%2,%3};"
                    : "+f"(acc[nt][0]), "+f"(acc[nt][1]), "+f"(acc[nt][2]), "+f"(acc[nt][3])
                    : "r"(a0), "r"(a1), "r"(a2), "r"(a3), "r"(b0), "r"(b1));
                asm volatile(
                    "mma.sync.aligned.m16n8k16.row.col.f32.f16.f16.f32 "
                    "{%0,%1,%2,%3}, {%4,%5,%6,%7}, {%8,%9}, {%0,%1,%2,%3};"
                    : "+f"(acc[nt + 1][0]), "+f"(acc[nt + 1][1]), "+f"(acc[nt + 1][2]), "+f"(acc[nt + 1][3])
                    : "r"(a0), "r"(a1), "r"(a2), "r"(a3), "r"(b2), "r"(b3));
            }
        }
    }

    int r0 = row0 + m0 + (lane >> 2);
    int cb = (lane & 3) * 2;
    float d0, d1;
    if (F32IN) {
        // dinv from degree directly -> no dependency on the scan chain
        d0 = (r0 < NN) ? rsqrtf((float)(g_deg[r0] + 1)) : 0.f;
        d1 = (r0 + 8 < NN) ? rsqrtf((float)(g_deg[r0 + 8] + 1)) : 0.f;
    } else {
        d0 = (r0 < NN) ? g_dinv[r0] : 0.f;
        d1 = (r0 + 8 < NN) ? g_dinv[r0 + 8] : 0.f;
    }
#pragma unroll
    for (int nt = 0; nt < 16; nt++) {
        if (r0 < NN)
            *(__half2*)&Y[(size_t)r0 * 128 + nt * 8 + cb] =
                __floats2half2_rn(acc[nt][0] * d0, acc[nt][1] * d0);
        if (r0 + 8 < NN)
            *(__half2*)&Y[(size_t)(r0 + 8) * 128 + nt * 8 + cb] =
                __floats2half2_rn(acc[nt][2] * d1, acc[nt][3] * d1);
    }
}

// ---------------- aggregation + folded-BN + ReLU (2 nodes per warp) --------
// 16 lanes x uint4 (LDG.128) per node row. t' pre-scaled by dinv[src].
template <bool FINAL>
__global__ void __launch_bounds__(256) k_agg16(const float* __restrict__ beta,
                                               const float* __restrict__ Wl,
                                               const int* __restrict__ batch) {
    int warp = (blockIdx.x * blockDim.x + threadIdx.x) >> 5;
    int lane = threadIdx.x & 31;
    int half = lane >> 4;
    int sub = lane & 15;
    int node = warp * 2 + half;
    if (node >= NN) return;

    const uint4* T = (const uint4*)g_t;   // 16 x uint4 (8 halves) per row
    float di = g_dinv[node];

    float acc[8];
    {
        uint4 u = T[(size_t)node * 16 + sub];   // self term t'[i]
        const __half2* p = (const __half2*)&u;
#pragma unroll
        for (int q = 0; q < 4; q++) {
            float2 f = __half22float2(p[q]);
            acc[q * 2] = f.x; acc[q * 2 + 1] = f.y;
        }
    }

    int e = g_rowptr[node];
    int e1 = g_rowptr[node + 1];

    for (; e + 8 <= e1; e += 8) {
        int s[8];
        uint4 v[8];
#pragma unroll
        for (int j = 0; j < 8; j++) s[j] = __ldg(&g_col[e + j]);
#pragma unroll
        for (int j = 0; j < 8; j++) v[j] = T[(size_t)s[j] * 16 + sub];
#pragma unroll
        for (int j = 0; j < 8; j++) {
            const __half2* p = (const __half2*)&v[j];
#pragma unroll
            for (int q = 0; q < 4; q++) {
                float2 f = __half22float2(p[q]);
                acc[q * 2] += f.x; acc[q * 2 + 1] += f.y;
            }
        }
    }
    for (; e + 4 <= e1; e += 4) {
        int s[4];
        uint4 v[4];
#pragma unroll
        for (int j = 0; j < 4; j++) s[j] = __ldg(&g_col[e + j]);
#pragma unroll
        for (int j = 0; j < 4; j++) v[j] = T[(size_t)s[j] * 16 + sub];
#pragma unroll
        for (int j = 0; j < 4; j++) {
            const __half2* p = (const __half2*)&v[j];
#pragma unroll
            for (int q = 0; q < 4; q++) {
                float2 f = __half22float2(p[q]);
                acc[q * 2] += f.x; acc[q * 2 + 1] += f.y;
            }
        }
    }
    for (; e < e1; ++e) {
        int s = __ldg(&g_col[e]);
        uint4 v = T[(size_t)s * 16 + sub];
        const __half2* p = (const __half2*)&v;
#pragma unroll
        for (int q = 0; q < 4; q++) {
            float2 f = __half22float2(p[q]);
            acc[q * 2] += f.x; acc[q * 2 + 1] += f.y;
        }
    }

    float4 be0 = ((const float4*)beta)[sub * 2];
    float4 be1v = ((const float4*)beta)[sub * 2 + 1];
    float y[8];
    y[0] = fmaxf(0.f, fmaf(di, acc[0], be0.x));
    y[1] = fmaxf(0.f, fmaf(di, acc[1], be0.y));
    y[2] = fmaxf(0.f, fmaf(di, acc[2], be0.z));
    y[3] = fmaxf(0.f, fmaf(di, acc[3], be0.w));
    y[4] = fmaxf(0.f, fmaf(di, acc[4], be1v.x));
    y[5] = fmaxf(0.f, fmaf(di, acc[5], be1v.y));
    y[6] = fmaxf(0.f, fmaf(di, acc[6], be1v.z));
    y[7] = fmaxf(0.f, fmaf(di, acc[7], be1v.w));

    if (!FINAL) {
        uint4 o;
        __half2* p = (__half2*)&o;
        p[0] = __floats2half2_rn(y[0], y[1]);
        p[1] = __floats2half2_rn(y[2], y[3]);
        p[2] = __floats2half2_rn(y[4], y[5]);
        p[3] = __floats2half2_rn(y[6], y[7]);
        ((uint4*)g_h)[(size_t)node * 16 + sub] = o;
    } else {
        float4 wl0 = ((const float4*)Wl)[sub * 2];
        float4 wl1 = ((const float4*)Wl)[sub * 2 + 1];
        float s = y[0] * wl0.x + y[1] * wl0.y + y[2] * wl0.z + y[3] * wl0.w +
                  y[4] * wl1.x + y[5] * wl1.y + y[6] * wl1.z + y[7] * wl1.w;
        unsigned mask = half ? 0xFFFF0000u : 0x0000FFFFu;
#pragma unroll
        for (int off = 8; off > 0; off >>= 1)
            s += __shfl_xor_sync(mask, s, off);
        if (sub == 0) atomicAdd(&g_gsum[batch[node]], s);
    }
}

__global__ void k_final(float* __restrict__ out, const float* __restrict__ bl) {
    int g = blockIdx.x * blockDim.x + threadIdx.x;
    if (g < GG) out[g] = g_gsum[g] / fmaxf((float)g_gcnt[g], 1.0f) + bl[0];
}

// ---------------- host launcher --------------------------------------------
extern "C" void kernel_launch(void* const* d_in, const int* in_sizes, int n_in,
                              void* d_out, int out_size) {
    const float* x     = (const float*)d_in[0];
    const int*   ei    = (const int*)d_in[1];
    const int*   batch = (const int*)d_in[2];
    const float* W1 = (const float*)d_in[3];
    const float* b1 = (const float*)d_in[4];
    const float* g1 = (const float*)d_in[5];
    const float* be1 = (const float*)d_in[6];
    const float* m1 = (const float*)d_in[7];
    const float* v1 = (const float*)d_in[8];
    const float* W2 = (const float*)d_in[9];
    const float* b2 = (const float*)d_in[10];
    const float* g2 = (const float*)d_in[11];
    const float* be2 = (const float*)d_in[12];
    const float* m2 = (const float*)d_in[13];
    const float* v2 = (const float*)d_in[14];
    const float* W3 = (const float*)d_in[15];
    const float* b3 = (const float*)d_in[16];
    const float* g3 = (const float*)d_in[17];
    const float* be3 = (const float*)d_in[18];
    const float* m3 = (const float*)d_in[19];
    const float* v3 = (const float*)d_in[20];
    const float* Wl = (const float*)d_in[21];
    const float* bl = (const float*)d_in[22];

    __half *t, *h, *Wh;
    float *beta;
    cudaGetSymbolAddress((void**)&t, g_t);
    cudaGetSymbolAddress((void**)&h, g_h);
    cudaGetSymbolAddress((void**)&Wh, g_Wh);
    cudaGetSymbolAddress((void**)&beta, g_beta);

    const int GEMM_SMEM = 2 * 128 * 136 * (int)sizeof(__half);   // 69632
    cudaFuncSetAttribute(k_gemm_tc<true>,  cudaFuncAttributeMaxDynamicSharedMemorySize, GEMM_SMEM);
    cudaFuncSetAttribute(k_gemm_tc<false>, cudaFuncAttributeMaxDynamicSharedMemorySize, GEMM_SMEM);

    static cudaStream_t s1 = nullptr;
    static cudaEvent_t evStart = nullptr, evHist = nullptr, evG1 = nullptr;
    if (s1 == nullptr) {
        cudaStreamCreateWithFlags(&s1, cudaStreamNonBlocking);
        cudaEventCreateWithFlags(&evStart, cudaEventDisableTiming);
        cudaEventCreateWithFlags(&evHist, cudaEventDisableTiming);
        cudaEventCreateWithFlags(&evG1, cudaEventDisableTiming);
    }

    const int TPB = 256;
    const int GEMM_BLOCKS = (NN + 127) / 128;                    // 782
    const int AGG_BLOCKS = ((NN + 1) / 2 * 32 + TPB - 1) / TPB;  // 6250

    // ---- fork: side stream handles weight prep (input-only dependency)
    cudaEventRecord(evStart, 0);
    cudaStreamWaitEvent(s1, evStart, 0);
    {
        dim3 grid(64, 3);
        k_prep_w<<<grid, 256, 0, s1>>>(W1, W2, W3, b1, b2, b3, g1, g2, g3,
                                       be1, be2, be3, m1, m2, m3, v1, v2, v3);
    }

    // ---- main stream: graph preprocessing
    k_zero<<<(NN + TPB - 1) / TPB, TPB>>>();
    k_hist<<<(EE / 4 + TPB - 1) / TPB, TPB>>>(ei, batch);
    cudaEventRecord(evHist, 0);                         // gemm1 needs only g_deg
    k_scan_local<<<NB, SCAN_B>>>();                     // produces dinv + scan
    k_scan_part<<<1, 128>>>();
    k_scan_add<<<(NN + TPB) / TPB, TPB>>>();
    k_fill<<<(EE + TPB - 1) / TPB, TPB>>>(ei);

    // ---- side stream: gemm1 (needs Wh + deg), overlaps the whole scan chain
    cudaStreamWaitEvent(s1, evHist, 0);
    k_gemm_tc<true><<<GEMM_BLOCKS, 256, GEMM_SMEM, s1>>>(x, Wh, t);
    cudaEventRecord(evG1, s1);

    // ---- join, then layers (serial on main stream)
    cudaStreamWaitEvent(0, evG1, 0);
    k_agg16<false><<<AGG_BLOCKS, TPB>>>(beta, nullptr, nullptr);
    k_gemm_tc<false><<<GEMM_BLOCKS, 256, GEMM_SMEM>>>(h, Wh + HH * HH, t);
    k_agg16<false><<<AGG_BLOCKS, TPB>>>(beta + HH, nullptr, nullptr);
    k_gemm_tc<false><<<GEMM_BLOCKS, 256, GEMM_SMEM>>>(h, Wh + 2 * HH * HH, t);
    k_agg16<true><<<AGG_BLOCKS, TPB>>>(beta + 2 * HH, Wl, batch);

    k_final<<<(GG + TPB - 1) / TPB, TPB>>>((float*)d_out, bl);
}

// round 16
// speedup vs baseline: 1.2087x; 1.0343x over previous
#include <cuda_runtime.h>
#include <cuda_fp16.h>
#include <cstdint>

#define NN 100000
#define EE 1600000
#define HH 128
#define GG 512
#define BN_EPS 1e-5f
#define SCAN_B 1024
#define NB ((NN + SCAN_B - 1) / SCAN_B)   // 98 scan blocks

// ---------------- scratch (device globals: no allocation allowed) -----------
__device__ __half g_t[(size_t)NN * HH];   // GEMM output t' = dinv .* (h @ W') (fp16)
__device__ __half g_h[(size_t)NN * HH];   // activated hidden (fp16)
__device__ __half g_Wh[3 * HH * HH];      // BN-folded fp16 weights
__device__ float  g_beta[3 * HH];         // BN-folded shifts
__device__ float  g_dinv[NN];
__device__ int    g_deg[NN];
__device__ int    g_rowptr[NN + 1];
__device__ int    g_cursor[NN];
__device__ int    g_col[EE];
__device__ float  g_gsum[GG];
__device__ int    g_gcnt[GG];
__device__ int    g_part[NB];

__device__ __forceinline__ uint32_t s2u(const void* p) {
    return (uint32_t)__cvta_generic_to_shared(p);
}

// ---------------- preprocessing kernels ------------------------------------
__global__ void k_zero() {
    int i = blockIdx.x * blockDim.x + threadIdx.x;
    if (i < NN) g_deg[i] = 0;
    if (i < GG) { g_gsum[i] = 0.0f; g_gcnt[i] = 0; }
}

__global__ void k_hist(const int* __restrict__ ei, const int* __restrict__ batch) {
    int e = blockIdx.x * blockDim.x + threadIdx.x;
    if (e < EE) atomicAdd(&g_deg[ei[EE + e]], 1);
    if (e < NN) atomicAdd(&g_gcnt[batch[e]], 1);
}

__global__ void k_scan_local() {
    __shared__ int sh[SCAN_B];
    int tx = threadIdx.x;
    int i = blockIdx.x * SCAN_B + tx;
    int v = (i < NN) ? g_deg[i] : 0;
    if (i < NN) g_dinv[i] = rsqrtf((float)(v + 1));   // fused dinv (+1 self-loop)
    sh[tx] = v;
    __syncthreads();
    for (int off = 1; off < SCAN_B; off <<= 1) {
        int t = (tx >= off) ? sh[tx - off] : 0;
        __syncthreads();
        sh[tx] += t;
        __syncthreads();
    }
    if (i < NN) g_rowptr[i] = sh[tx] - v;        // exclusive
    if (tx == SCAN_B - 1) g_part[blockIdx.x] = sh[tx];
}

__global__ void k_scan_part() {
    __shared__ int sh[128];
    int tx = threadIdx.x;
    int v = (tx < NB) ? g_part[tx] : 0;
    sh[tx] = v;
    __syncthreads();
    for (int off = 1; off < 128; off <<= 1) {
        int t = (tx >= off) ? sh[tx - off] : 0;
        __syncthreads();
        sh[tx] += t;
        __syncthreads();
    }
    if (tx < NB) g_part[tx] = sh[tx] - v;        // exclusive block offsets
}

__global__ void k_scan_add() {
    int i = blockIdx.x * blockDim.x + threadIdx.x;
    if (i < NN) {
        int v = g_rowptr[i] + g_part[i >> 10];
        g_rowptr[i] = v;
        g_cursor[i] = v;
    }
    if (i == 0) g_rowptr[NN] = EE;
}

__global__ void k_fill(const int* __restrict__ ei) {
    int e = blockIdx.x * blockDim.x + threadIdx.x;
    if (e < EE) {
        int src = ei[e];
        int dst = ei[EE + e];
        int p = atomicAdd(&g_cursor[dst], 1);
        g_col[p] = src;
    }
}

// Fold BN scale into W columns (fp16) for all 3 layers, compute folded shifts.
__global__ void k_prep_w(const float* __restrict__ W1v, const float* __restrict__ W2v,
                         const float* __restrict__ W3v,
                         const float* __restrict__ b1v, const float* __restrict__ b2v,
                         const float* __restrict__ b3v,
                         const float* __restrict__ ga1, const float* __restrict__ ga2,
                         const float* __restrict__ ga3,
                         const float* __restrict__ be1, const float* __restrict__ be2,
                         const float* __restrict__ be3,
                         const float* __restrict__ m1v, const float* __restrict__ m2v,
                         const float* __restrict__ m3v,
                         const float* __restrict__ v1v, const float* __restrict__ v2v,
                         const float* __restrict__ v3v) {
    int layer = blockIdx.y;
    const float* W  = layer == 0 ? W1v : layer == 1 ? W2v : W3v;
    const float* b  = layer == 0 ? b1v : layer == 1 ? b2v : b3v;
    const float* ga = layer == 0 ? ga1 : layer == 1 ? ga2 : ga3;
    const float* be = layer == 0 ? be1 : layer == 1 ? be2 : be3;
    const float* m  = layer == 0 ? m1v : layer == 1 ? m2v : m3v;
    const float* v  = layer == 0 ? v1v : layer == 1 ? v2v : v3v;
    int idx = blockIdx.x * blockDim.x + threadIdx.x;
    if (idx < HH * HH) {
        int n = idx & (HH - 1);
        float alpha = ga[n] * rsqrtf(v[n] + BN_EPS);
        g_Wh[layer * HH * HH + idx] = __float2half(W[idx] * alpha);
    }
    if (idx < HH) {
        float alpha = ga[idx] * rsqrtf(v[idx] + BN_EPS);
        g_beta[layer * HH + idx] = (b[idx] - m[idx]) * alpha + be[idx];
    }
}

// ---------------- fp16 tensor-core GEMM + dinv prescale epilogue -----------
// Y[i,:] = dinv[i] * (X[i,:] @ W).
// Warp tiling: m32 x n64 per warp (wid&3 -> m-group, wid>>2 -> n-half).
// B fragments shared across only the warp's n-half: 6 ldsm/warp/ks vs 9.
// F32IN (layer 1): bulk sync loads + dinv from g_deg (depends only on hist).
// !F32IN: cp.async 2-stage K-split; reads g_dinv.
template <bool F32IN>
__global__ void __launch_bounds__(256) k_gemm_tc(const void* __restrict__ Xv,
                                                 const __half* __restrict__ W,
                                                 __half* __restrict__ Y) {
    extern __shared__ __half sh[];
    __half* As = sh;               // 128 x 136 (272 B pitch)
    __half* Ws = sh + 128 * 136;   // 128 x 136 (row = k, cols = n)

    int tid = threadIdx.x;
    int row0 = blockIdx.x * 128;

    if (F32IN) {
        const uint4* Wg = (const uint4*)W;
#pragma unroll
        for (int i = 0; i < 8; i++) {
            int idx = i * 256 + tid;
            int r = idx >> 4, c = (idx & 15) * 8;
            *(uint4*)&Ws[r * 136 + c] = Wg[idx];
        }
        const float4* Xg = (const float4*)Xv;
#pragma unroll
        for (int i = 0; i < 16; i++) {
            int idx = i * 256 + tid;
            int r = idx >> 5, c = (idx & 31) * 4;
            float4 v = make_float4(0.f, 0.f, 0.f, 0.f);
            if (row0 + r < NN) v = Xg[(size_t)(row0 + r) * 32 + (idx & 31)];
            *(__half2*)&As[r * 136 + c]     = __floats2half2_rn(v.x, v.y);
            *(__half2*)&As[r * 136 + c + 2] = __floats2half2_rn(v.z, v.w);
        }
        __syncthreads();
    } else {
        const char* Ag = (const char*)Xv;     // 256 B per row (k bytes)
        const char* Wg = (const char*)W;      // 256 B per row (row = k, bytes = n)
#pragma unroll
        for (int h = 0; h < 2; h++) {
#pragma unroll
            for (int i = 0; i < 4; i++) {     // A: 1024 chunks
                int idx = i * 256 + tid;
                int r = idx >> 3, ch = idx & 7;
                uint32_t saddr = s2u(&As[0]) + r * 272 + h * 128 + ch * 16;
                const char* gaddr = Ag + (size_t)(row0 + r) * 256 + h * 128 + ch * 16;
                int sz = (row0 + r < NN) ? 16 : 0;
                asm volatile("cp.async.cg.shared.global [%0], [%1], 16, %2;"
                             :: "r"(saddr), "l"(gaddr), "r"(sz));
            }
#pragma unroll
            for (int i = 0; i < 4; i++) {     // W: 64 rows x 16 chunks
                int idx = i * 256 + tid;
                int r = h * 64 + (idx >> 4);
                int ch = idx & 15;
                uint32_t saddr = s2u(&Ws[0]) + r * 272 + ch * 16;
                const char* gaddr = Wg + (size_t)r * 256 + ch * 16;
                asm volatile("cp.async.cg.shared.global [%0], [%1], 16;"
                             :: "r"(saddr), "l"(gaddr));
            }
            asm volatile("cp.async.commit_group;");
        }
    }

    int wid = tid >> 5, lane = tid & 31;
    int m0 = (wid & 3) * 32;       // warp's 32-row group
    int nc0 = (wid >> 2) * 64;     // warp's 64-col half

    float acc[2][8][4];
#pragma unroll
    for (int mt = 0; mt < 2; mt++)
#pragma unroll
        for (int nt = 0; nt < 8; nt++)
#pragma unroll
            for (int c = 0; c < 4; c++) acc[mt][nt][c] = 0.f;

#pragma unroll
    for (int h = 0; h < 2; h++) {
        if (!F32IN) {
            if (h == 0) { asm volatile("cp.async.wait_group 1;"); }
            else        { asm volatile("cp.async.wait_group 0;"); }
            __syncthreads();
        }
#pragma unroll
        for (int ksl = 0; ksl < 4; ksl++) {
            int ks = h * 4 + ksl;
            // A fragments: 2 m16 tiles
            uint32_t a[2][4];
#pragma unroll
            for (int mt = 0; mt < 2; mt++) {
                uint32_t aaddr = s2u(&As[(m0 + mt * 16 + (lane & 15)) * 136 +
                                         ks * 16 + (lane >> 4) * 8]);
                asm volatile("ldmatrix.sync.aligned.m8n8.x4.shared.b16 {%0,%1,%2,%3}, [%4];"
                             : "=r"(a[mt][0]), "=r"(a[mt][1]), "=r"(a[mt][2]), "=r"(a[mt][3])
                             : "r"(aaddr));
            }
            // B fragments: 4 x (16-col group) covering this warp's n64
#pragma unroll
            for (int g = 0; g < 4; g++) {
                uint32_t b0, b1, b2, b3;
                uint32_t baddr = s2u(&Ws[(ks * 16 + (lane & 15)) * 136 +
                                         nc0 + g * 16 + (lane >> 4) * 8]);
                asm volatile("ldmatrix.sync.aligned.m8n8.x4.trans.shared.b16 {%0,%1,%2,%3}, [%4];"
                             : "=r"(b0), "=r"(b1), "=r"(b2), "=r"(b3) : "r"(baddr));
#pragma unroll
                for (int mt = 0; mt < 2; mt++) {
                    int nt = g * 2;
                    asm volatile(
                        "mma.sync.aligned.m16n8k16.row.col.f32.f16.f16.f32 "
                        "{%0,%1,%2,%3}, {%4,%5,%6,%7}, {%8,%9}, {%0,%1,%2,%3};"
                        : "+f"(acc[mt][nt][0]), "+f"(acc[mt][nt][1]),
                          "+f"(acc[mt][nt][2]), "+f"(acc[mt][nt][3])
                        : "r"(a[mt][0]), "r"(a[mt][1]), "r"(a[mt][2]), "r"(a[mt][3]),
                          "r"(b0), "r"(b1));
                    asm volatile(
                        "mma.sync.aligned.m16n8k16.row.col.f32.f16.f16.f32 "
                        "{%0,%1,%2,%3}, {%4,%5,%6,%7}, {%8,%9}, {%0,%1,%2,%3};"
                        : "+f"(acc[mt][nt + 1][0]), "+f"(acc[mt][nt + 1][1]),
                          "+f"(acc[mt][nt + 1][2]), "+f"(acc[mt][nt + 1][3])
                        : "r"(a[mt][0]), "r"(a[mt][1]), "r"(a[mt][2]), "r"(a[mt][3]),
                          "r"(b2), "r"(b3));
                }
            }
        }
    }

    int cb = (lane & 3) * 2;
#pragma unroll
    for (int mt = 0; mt < 2; mt++) {
        int r0 = row0 + m0 + mt * 16 + (lane >> 2);
        float d0, d1;
        if (F32IN) {
            d0 = (r0 < NN) ? rsqrtf((float)(g_deg[r0] + 1)) : 0.f;
            d1 = (r0 + 8 < NN) ? rsqrtf((float)(g_deg[r0 + 8] + 1)) : 0.f;
        } else {
            d0 = (r0 < NN) ? g_dinv[r0] : 0.f;
            d1 = (r0 + 8 < NN) ? g_dinv[r0 + 8] : 0.f;
        }
#pragma unroll
        for (int nt = 0; nt < 8; nt++) {
            int col = nc0 + nt * 8 + cb;
            if (r0 < NN)
                *(__half2*)&Y[(size_t)r0 * 128 + col] =
                    __floats2half2_rn(acc[mt][nt][0] * d0, acc[mt][nt][1] * d0);
            if (r0 + 8 < NN)
                *(__half2*)&Y[(size_t)(r0 + 8) * 128 + col] =
                    __floats2half2_rn(acc[mt][nt][2] * d1, acc[mt][nt][3] * d1);
        }
    }
}

// ---------------- aggregation + folded-BN + ReLU (2 nodes per warp) --------
// 16 lanes x uint4 (LDG.128) per node row. t' pre-scaled by dinv[src].
template <bool FINAL>
__global__ void __launch_bounds__(256) k_agg16(const float* __restrict__ beta,
                                               const float* __restrict__ Wl,
                                               const int* __restrict__ batch) {
    int warp = (blockIdx.x * blockDim.x + threadIdx.x) >> 5;
    int lane = threadIdx.x & 31;
    int half = lane >> 4;
    int sub = lane & 15;
    int node = warp * 2 + half;
    if (node >= NN) return;

    const uint4* T = (const uint4*)g_t;   // 16 x uint4 (8 halves) per row
    float di = g_dinv[node];

    float acc[8];
    {
        uint4 u = T[(size_t)node * 16 + sub];   // self term t'[i]
        const __half2* p = (const __half2*)&u;
#pragma unroll
        for (int q = 0; q < 4; q++) {
            float2 f = __half22float2(p[q]);
            acc[q * 2] = f.x; acc[q * 2 + 1] = f.y;
        }
    }

    int e = g_rowptr[node];
    int e1 = g_rowptr[node + 1];

    for (; e + 8 <= e1; e += 8) {
        int s[8];
        uint4 v[8];
#pragma unroll
        for (int j = 0; j < 8; j++) s[j] = __ldg(&g_col[e + j]);
#pragma unroll
        for (int j = 0; j < 8; j++) v[j] = T[(size_t)s[j] * 16 + sub];
#pragma unroll
        for (int j = 0; j < 8; j++) {
            const __half2* p = (const __half2*)&v[j];
#pragma unroll
            for (int q = 0; q < 4; q++) {
                float2 f = __half22float2(p[q]);
                acc[q * 2] += f.x; acc[q * 2 + 1] += f.y;
            }
        }
    }
    for (; e + 4 <= e1; e += 4) {
        int s[4];
        uint4 v[4];
#pragma unroll
        for (int j = 0; j < 4; j++) s[j] = __ldg(&g_col[e + j]);
#pragma unroll
        for (int j = 0; j < 4; j++) v[j] = T[(size_t)s[j] * 16 + sub];
#pragma unroll
        for (int j = 0; j < 4; j++) {
            const __half2* p = (const __half2*)&v[j];
#pragma unroll
            for (int q = 0; q < 4; q++) {
                float2 f = __half22float2(p[q]);
                acc[q * 2] += f.x; acc[q * 2 + 1] += f.y;
            }
        }
    }
    for (; e < e1; ++e) {
        int s = __ldg(&g_col[e]);
        uint4 v = T[(size_t)s * 16 + sub];
        const __half2* p = (const __half2*)&v;
#pragma unroll
        for (int q = 0; q < 4; q++) {
            float2 f = __half22float2(p[q]);
            acc[q * 2] += f.x; acc[q * 2 + 1] += f.y;
        }
    }

    float4 be0 = ((const float4*)beta)[sub * 2];
    float4 be1v = ((const float4*)beta)[sub * 2 + 1];
    float y[8];
    y[0] = fmaxf(0.f, fmaf(di, acc[0], be0.x));
    y[1] = fmaxf(0.f, fmaf(di, acc[1], be0.y));
    y[2] = fmaxf(0.f, fmaf(di, acc[2], be0.z));
    y[3] = fmaxf(0.f, fmaf(di, acc[3], be0.w));
    y[4] = fmaxf(0.f, fmaf(di, acc[4], be1v.x));
    y[5] = fmaxf(0.f, fmaf(di, acc[5], be1v.y));
    y[6] = fmaxf(0.f, fmaf(di, acc[6], be1v.z));
    y[7] = fmaxf(0.f, fmaf(di, acc[7], be1v.w));

    if (!FINAL) {
        uint4 o;
        __half2* p = (__half2*)&o;
        p[0] = __floats2half2_rn(y[0], y[1]);
        p[1] = __floats2half2_rn(y[2], y[3]);
        p[2] = __floats2half2_rn(y[4], y[5]);
        p[3] = __floats2half2_rn(y[6], y[7]);
        ((uint4*)g_h)[(size_t)node * 16 + sub] = o;
    } else {
        float4 wl0 = ((const float4*)Wl)[sub * 2];
        float4 wl1 = ((const float4*)Wl)[sub * 2 + 1];
        float s = y[0] * wl0.x + y[1] * wl0.y + y[2] * wl0.z + y[3] * wl0.w +
                  y[4] * wl1.x + y[5] * wl1.y + y[6] * wl1.z + y[7] * wl1.w;
        unsigned mask = half ? 0xFFFF0000u : 0x0000FFFFu;
#pragma unroll
        for (int off = 8; off > 0; off >>= 1)
            s += __shfl_xor_sync(mask, s, off);
        if (sub == 0) atomicAdd(&g_gsum[batch[node]], s);
    }
}

__global__ void k_final(float* __restrict__ out, const float* __restrict__ bl) {
    int g = blockIdx.x * blockDim.x + threadIdx.x;
    if (g < GG) out[g] = g_gsum[g] / fmaxf((float)g_gcnt[g], 1.0f) + bl[0];
}

// ---------------- host launcher --------------------------------------------
extern "C" void kernel_launch(void* const* d_in, const int* in_sizes, int n_in,
                              void* d_out, int out_size) {
    const float* x     = (const float*)d_in[0];
    const int*   ei    = (const int*)d_in[1];
    const int*   batch = (const int*)d_in[2];
    const float* W1 = (const float*)d_in[3];
    const float* b1 = (const float*)d_in[4];
    const float* g1 = (const float*)d_in[5];
    const float* be1 = (const float*)d_in[6];
    const float* m1 = (const float*)d_in[7];
    const float* v1 = (const float*)d_in[8];
    const float* W2 = (const float*)d_in[9];
    const float* b2 = (const float*)d_in[10];
    const float* g2 = (const float*)d_in[11];
    const float* be2 = (const float*)d_in[12];
    const float* m2 = (const float*)d_in[13];
    const float* v2 = (const float*)d_in[14];
    const float* W3 = (const float*)d_in[15];
    const float* b3 = (const float*)d_in[16];
    const float* g3 = (const float*)d_in[17];
    const float* be3 = (const float*)d_in[18];
    const float* m3 = (const float*)d_in[19];
    const float* v3 = (const float*)d_in[20];
    const float* Wl = (const float*)d_in[21];
    const float* bl = (const float*)d_in[22];

    __half *t, *h, *Wh;
    float *beta;
    cudaGetSymbolAddress((void**)&t, g_t);
    cudaGetSymbolAddress((void**)&h, g_h);
    cudaGetSymbolAddress((void**)&Wh, g_Wh);
    cudaGetSymbolAddress((void**)&beta, g_beta);

    const int GEMM_SMEM = 2 * 128 * 136 * (int)sizeof(__half);   // 69632
    cudaFuncSetAttribute(k_gemm_tc<true>,  cudaFuncAttributeMaxDynamicSharedMemorySize, GEMM_SMEM);
    cudaFuncSetAttribute(k_gemm_tc<false>, cudaFuncAttributeMaxDynamicSharedMemorySize, GEMM_SMEM);

    static cudaStream_t s1 = nullptr;
    static cudaEvent_t evStart = nullptr, evHist = nullptr, evG1 = nullptr;
    if (s1 == nullptr) {
        cudaStreamCreateWithFlags(&s1, cudaStreamNonBlocking);
        cudaEventCreateWithFlags(&evStart, cudaEventDisableTiming);
        cudaEventCreateWithFlags(&evHist, cudaEventDisableTiming);
        cudaEventCreateWithFlags(&evG1, cudaEventDisableTiming);
    }

    const int TPB = 256;
    const int GEMM_BLOCKS = (NN + 127) / 128;                    // 782
    const int AGG_BLOCKS = ((NN + 1) / 2 * 32 + TPB - 1) / TPB;  // 6250

    // ---- fork: side stream handles weight prep (input-only dependency)
    cudaEventRecord(evStart, 0);
    cudaStreamWaitEvent(s1, evStart, 0);
    {
        dim3 grid(64, 3);
        k_prep_w<<<grid, 256, 0, s1>>>(W1, W2, W3, b1, b2, b3, g1, g2, g3,
                                       be1, be2, be3, m1, m2, m3, v1, v2, v3);
    }

    // ---- main stream: graph preprocessing
    k_zero<<<(NN + TPB - 1) / TPB, TPB>>>();
    k_hist<<<(EE + TPB - 1) / TPB, TPB>>>(ei, batch);
    cudaEventRecord(evHist, 0);                         // gemm1 needs only g_deg
    k_scan_local<<<NB, SCAN_B>>>();                     // produces dinv + scan
    k_scan_part<<<1, 128>>>();
    k_scan_add<<<(NN + TPB) / TPB, TPB>>>();
    k_fill<<<(EE + TPB - 1) / TPB, TPB>>>(ei);

    // ---- side stream: gemm1 (needs Wh + deg), overlaps the whole scan chain
    cudaStreamWaitEvent(s1, evHist, 0);
    k_gemm_tc<true><<<GEMM_BLOCKS, 256, GEMM_SMEM, s1>>>(x, Wh, t);
    cudaEventRecord(evG1, s1);

    // ---- join, then layers (serial on main stream)
    cudaStreamWaitEvent(0, evG1, 0);
    k_agg16<false><<<AGG_BLOCKS, TPB>>>(beta, nullptr, nullptr);
    k_gemm_tc<false><<<GEMM_BLOCKS, 256, GEMM_SMEM>>>(h, Wh + HH * HH, t);
    k_agg16<false><<<AGG_BLOCKS, TPB>>>(beta + HH, nullptr, nullptr);
    k_gemm_tc<false><<<GEMM_BLOCKS, 256, GEMM_SMEM>>>(h, Wh + 2 * HH * HH, t);
    k_agg16<true><<<AGG_BLOCKS, TPB>>>(beta + 2 * HH, Wl, batch);

    k_final<<<(GG + TPB - 1) / TPB, TPB>>>((float*)d_out, bl);
}

// round 17
// speedup vs baseline: 1.2256x; 1.0140x over previous
#include <cuda_runtime.h>
#include <cuda_fp16.h>
#include <cstdint>

#define NN 100000
#define EE 1600000
#define HH 128
#define GG 512
#define BN_EPS 1e-5f
#define SCAN_B 1024
#define NB ((NN + SCAN_B - 1) / SCAN_B)   // 98 scan blocks

// ---------------- scratch (device globals: no allocation allowed) -----------
__device__ __half g_t[(size_t)NN * HH];   // GEMM output t' = dinv .* (h @ W') (fp16)
__device__ __half g_h[(size_t)NN * HH];   // activated hidden (fp16)
__device__ __half g_Wh[3 * HH * HH];      // BN-folded fp16 weights
__device__ float  g_beta[3 * HH];         // BN-folded shifts
__device__ float  g_dinv[NN];
__device__ int    g_deg[NN];
__device__ int    g_rowptr[NN + 1];
__device__ int    g_cursor[NN];
__device__ int    g_col[EE];
__device__ float  g_gsum[GG];
__device__ int    g_gcnt[GG];
__device__ int    g_part[NB];

__device__ __forceinline__ uint32_t s2u(const void* p) {
    return (uint32_t)__cvta_generic_to_shared(p);
}

// ---------------- preprocessing kernels ------------------------------------
__global__ void k_zero() {
    int i = blockIdx.x * blockDim.x + threadIdx.x;
    if (i < NN) g_deg[i] = 0;
    if (i < GG) { g_gsum[i] = 0.0f; g_gcnt[i] = 0; }
}

__global__ void k_hist(const int* __restrict__ ei, const int* __restrict__ batch) {
    int e = blockIdx.x * blockDim.x + threadIdx.x;
    if (e < EE) atomicAdd(&g_deg[ei[EE + e]], 1);
    if (e < NN) atomicAdd(&g_gcnt[batch[e]], 1);
}

__global__ void k_scan_local() {
    __shared__ int sh[SCAN_B];
    int tx = threadIdx.x;
    int i = blockIdx.x * SCAN_B + tx;
    int v = (i < NN) ? g_deg[i] : 0;
    if (i < NN) g_dinv[i] = rsqrtf((float)(v + 1));   // fused dinv (+1 self-loop)
    sh[tx] = v;
    __syncthreads();
    for (int off = 1; off < SCAN_B; off <<= 1) {
        int t = (tx >= off) ? sh[tx - off] : 0;
        __syncthreads();
        sh[tx] += t;
        __syncthreads();
    }
    if (i < NN) g_rowptr[i] = sh[tx] - v;        // exclusive
    if (tx == SCAN_B - 1) g_part[blockIdx.x] = sh[tx];
}

__global__ void k_scan_part() {
    __shared__ int sh[128];
    int tx = threadIdx.x;
    int v = (tx < NB) ? g_part[tx] : 0;
    sh[tx] = v;
    __syncthreads();
    for (int off = 1; off < 128; off <<= 1) {
        int t = (tx >= off) ? sh[tx - off] : 0;
        __syncthreads();
        sh[tx] += t;
        __syncthreads();
    }
    if (tx < NB) g_part[tx] = sh[tx] - v;        // exclusive block offsets
}

__global__ void k_scan_add() {
    int i = blockIdx.x * blockDim.x + threadIdx.x;
    if (i < NN) {
        int v = g_rowptr[i] + g_part[i >> 10];
        g_rowptr[i] = v;
        g_cursor[i] = v;
    }
    if (i == 0) g_rowptr[NN] = EE;
}

__global__ void k_fill(const int* __restrict__ ei) {
    int e = blockIdx.x * blockDim.x + threadIdx.x;
    if (e < EE) {
        int src = ei[e];
        int dst = ei[EE + e];
        int p = atomicAdd(&g_cursor[dst], 1);
        g_col[p] = src;
    }
}

// Fold BN scale into W columns (fp16) for all 3 layers, compute folded shifts.
__global__ void k_prep_w(const float* __restrict__ W1v, const float* __restrict__ W2v,
                         const float* __restrict__ W3v,
                         const float* __restrict__ b1v, const float* __restrict__ b2v,
                         const float* __restrict__ b3v,
                         const float* __restrict__ ga1, const float* __restrict__ ga2,
                         const float* __restrict__ ga3,
                         const float* __restrict__ be1, const float* __restrict__ be2,
                         const float* __restrict__ be3,
                         const float* __restrict__ m1v, const float* __restrict__ m2v,
                         const float* __restrict__ m3v,
                         const float* __restrict__ v1v, const float* __restrict__ v2v,
                         const float* __restrict__ v3v) {
    int layer = blockIdx.y;
    const float* W  = layer == 0 ? W1v : layer == 1 ? W2v : W3v;
    const float* b  = layer == 0 ? b1v : layer == 1 ? b2v : b3v;
    const float* ga = layer == 0 ? ga1 : layer == 1 ? ga2 : ga3;
    const float* be = layer == 0 ? be1 : layer == 1 ? be2 : be3;
    const float* m  = layer == 0 ? m1v : layer == 1 ? m2v : m3v;
    const float* v  = layer == 0 ? v1v : layer == 1 ? v2v : v3v;
    int idx = blockIdx.x * blockDim.x + threadIdx.x;
    if (idx < HH * HH) {
        int n = idx & (HH - 1);
        float alpha = ga[n] * rsqrtf(v[n] + BN_EPS);
        g_Wh[layer * HH * HH + idx] = __float2half(W[idx] * alpha);
    }
    if (idx < HH) {
        float alpha = ga[idx] * rsqrtf(v[idx] + BN_EPS);
        g_beta[layer * HH + idx] = (b[idx] - m[idx]) * alpha + be[idx];
    }
}

// ---------------- fp16 tensor-core GEMM + dinv prescale epilogue -----------
// Y[i,:] = dinv[i] * (X[i,:] @ W).
// Warp tiling: m32 x n64 per warp (wid&3 -> m-group, wid>>2 -> n-half).
// F32IN (layer 1): bulk sync loads + dinv from g_deg (depends only on hist).
// !F32IN: cp.async 4-stage K-pipeline (32 k-cols per stage): first MMA
// starts after 1/4 of the data; 3 stages of prefetch depth thereafter.
template <bool F32IN>
__global__ void __launch_bounds__(256, 2) k_gemm_tc(const void* __restrict__ Xv,
                                                    const __half* __restrict__ W,
                                                    __half* __restrict__ Y) {
    extern __shared__ __half sh[];
    __half* As = sh;               // 128 x 136 (272 B pitch)
    __half* Ws = sh + 128 * 136;   // 128 x 136 (row = k, cols = n)

    int tid = threadIdx.x;
    int row0 = blockIdx.x * 128;

    if (F32IN) {
        const uint4* Wg = (const uint4*)W;
#pragma unroll
        for (int i = 0; i < 8; i++) {
            int idx = i * 256 + tid;
            int r = idx >> 4, c = (idx & 15) * 8;
            *(uint4*)&Ws[r * 136 + c] = Wg[idx];
        }
        const float4* Xg = (const float4*)Xv;
#pragma unroll
        for (int i = 0; i < 16; i++) {
            int idx = i * 256 + tid;
            int r = idx >> 5, c = (idx & 31) * 4;
            float4 v = make_float4(0.f, 0.f, 0.f, 0.f);
            if (row0 + r < NN) v = Xg[(size_t)(row0 + r) * 32 + (idx & 31)];
            *(__half2*)&As[r * 136 + c]     = __floats2half2_rn(v.x, v.y);
            *(__half2*)&As[r * 136 + c + 2] = __floats2half2_rn(v.z, v.w);
        }
        __syncthreads();
    } else {
        const char* Ag = (const char*)Xv;     // 256 B per row (k bytes)
        const char* Wg = (const char*)W;      // 256 B per row (row = k, bytes = n)
#pragma unroll
        for (int q = 0; q < 4; q++) {
            // A: 128 rows, byte range [q*64, q*64+64) = k cols [q*32, q*32+32)
#pragma unroll
            for (int i = 0; i < 2; i++) {     // 512 chunks
                int idx = i * 256 + tid;
                int r = idx >> 2, ch = idx & 3;
                uint32_t saddr = s2u(&As[0]) + r * 272 + q * 64 + ch * 16;
                const char* gaddr = Ag + (size_t)(row0 + r) * 256 + q * 64 + ch * 16;
                int sz = (row0 + r < NN) ? 16 : 0;
                asm volatile("cp.async.cg.shared.global [%0], [%1], 16, %2;"
                             :: "r"(saddr), "l"(gaddr), "r"(sz));
            }
            // W: k rows [q*32, q*32+32), full 256 B each
#pragma unroll
            for (int i = 0; i < 2; i++) {     // 512 chunks
                int idx = i * 256 + tid;
                int r = q * 32 + (idx >> 4);
                int ch = idx & 15;
                uint32_t saddr = s2u(&Ws[0]) + r * 272 + ch * 16;
                const char* gaddr = Wg + (size_t)r * 256 + ch * 16;
                asm volatile("cp.async.cg.shared.global [%0], [%1], 16;"
                             :: "r"(saddr), "l"(gaddr));
            }
            asm volatile("cp.async.commit_group;");
        }
    }

    int wid = tid >> 5, lane = tid & 31;
    int m0 = (wid & 3) * 32;       // warp's 32-row group
    int nc0 = (wid >> 2) * 64;     // warp's 64-col half

    float acc[2][8][4];
#pragma unroll
    for (int mt = 0; mt < 2; mt++)
#pragma unroll
        for (int nt = 0; nt < 8; nt++)
#pragma unroll
            for (int c = 0; c < 4; c++) acc[mt][nt][c] = 0.f;

#pragma unroll
    for (int q = 0; q < 4; q++) {
        if (!F32IN) {
            if (q == 0)      { asm volatile("cp.async.wait_group 3;"); }
            else if (q == 1) { asm volatile("cp.async.wait_group 2;"); }
            else if (q == 2) { asm volatile("cp.async.wait_group 1;"); }
            else             { asm volatile("cp.async.wait_group 0;"); }
            __syncthreads();
        }
#pragma unroll
        for (int ksl = 0; ksl < 2; ksl++) {
            int ks = q * 2 + ksl;
            // A fragments: 2 m16 tiles
            uint32_t a[2][4];
#pragma unroll
            for (int mt = 0; mt < 2; mt++) {
                uint32_t aaddr = s2u(&As[(m0 + mt * 16 + (lane & 15)) * 136 +
                                         ks * 16 + (lane >> 4) * 8]);
                asm volatile("ldmatrix.sync.aligned.m8n8.x4.shared.b16 {%0,%1,%2,%3}, [%4];"
                             : "=r"(a[mt][0]), "=r"(a[mt][1]), "=r"(a[mt][2]), "=r"(a[mt][3])
                             : "r"(aaddr));
            }
            // B fragments: 4 x (16-col group) covering this warp's n64
#pragma unroll
            for (int g = 0; g < 4; g++) {
                uint32_t b0, b1, b2, b3;
                uint32_t baddr = s2u(&Ws[(ks * 16 + (lane & 15)) * 136 +
                                         nc0 + g * 16 + (lane >> 4) * 8]);
                asm volatile("ldmatrix.sync.aligned.m8n8.x4.trans.shared.b16 {%0,%1,%2,%3}, [%4];"
                             : "=r"(b0), "=r"(b1), "=r"(b2), "=r"(b3) : "r"(baddr));
#pragma unroll
                for (int mt = 0; mt < 2; mt++) {
                    int nt = g * 2;
                    asm volatile(
                        "mma.sync.aligned.m16n8k16.row.col.f32.f16.f16.f32 "
                        "{%0,%1,%2,%3}, {%4,%5,%6,%7}, {%8,%9}, {%0,%1,%2,%3};"
                        : "+f"(acc[mt][nt][0]), "+f"(acc[mt][nt][1]),
                          "+f"(acc[mt][nt][2]), "+f"(acc[mt][nt][3])
                        : "r"(a[mt][0]), "r"(a[mt][1]), "r"(a[mt][2]), "r"(a[mt][3]),
                          "r"(b0), "r"(b1));
                    asm volatile(
                        "mma.sync.aligned.m16n8k16.row.col.f32.f16.f16.f32 "
                        "{%0,%1,%2,%3}, {%4,%5,%6,%7}, {%8,%9}, {%0,%1,%2,%3};"
                        : "+f"(acc[mt][nt + 1][0]), "+f"(acc[mt][nt + 1][1]),
                          "+f"(acc[mt][nt + 1][2]), "+f"(acc[mt][nt + 1][3])
                        : "r"(a[mt][0]), "r"(a[mt][1]), "r"(a[mt][2]), "r"(a[mt][3]),
                          "r"(b2), "r"(b3));
                }
            }
        }
    }

    int cb = (lane & 3) * 2;
#pragma unroll
    for (int mt = 0; mt < 2; mt++) {
        int r0 = row0 + m0 + mt * 16 + (lane >> 2);
        float d0, d1;
        if (F32IN) {
            d0 = (r0 < NN) ? rsqrtf((float)(g_deg[r0] + 1)) : 0.f;
            d1 = (r0 + 8 < NN) ? rsqrtf((float)(g_deg[r0 + 8] + 1)) : 0.f;
        } else {
            d0 = (r0 < NN) ? g_dinv[r0] : 0.f;
            d1 = (r0 + 8 < NN) ? g_dinv[r0 + 8] : 0.f;
        }
#pragma unroll
        for (int nt = 0; nt < 8; nt++) {
            int col = nc0 + nt * 8 + cb;
            if (r0 < NN)
                *(__half2*)&Y[(size_t)r0 * 128 + col] =
                    __floats2half2_rn(acc[mt][nt][0] * d0, acc[mt][nt][1] * d0);
            if (r0 + 8 < NN)
                *(__half2*)&Y[(size_t)(r0 + 8) * 128 + col] =
                    __floats2half2_rn(acc[mt][nt][2] * d1, acc[mt][nt][3] * d1);
        }
    }
}

// ---------------- aggregation + folded-BN + ReLU (2 nodes per warp) --------
// 16 lanes x uint4 (LDG.128) per node row. t' pre-scaled by dinv[src].
template <bool FINAL>
__global__ void __launch_bounds__(256) k_agg16(const float* __restrict__ beta,
                                               const float* __restrict__ Wl,
                                               const int* __restrict__ batch) {
    int warp = (blockIdx.x * blockDim.x + threadIdx.x) >> 5;
    int lane = threadIdx.x & 31;
    int half = lane >> 4;
    int sub = lane & 15;
    int node = warp * 2 + half;
    if (node >= NN) return;

    const uint4* T = (const uint4*)g_t;   // 16 x uint4 (8 halves) per row
    float di = g_dinv[node];

    float acc[8];
    {
        uint4 u = T[(size_t)node * 16 + sub];   // self term t'[i]
        const __half2* p = (const __half2*)&u;
#pragma unroll
        for (int q = 0; q < 4; q++) {
            float2 f = __half22float2(p[q]);
            acc[q * 2] = f.x; acc[q * 2 + 1] = f.y;
        }
    }

    int e = g_rowptr[node];
    int e1 = g_rowptr[node + 1];

    for (; e + 8 <= e1; e += 8) {
        int s[8];
        uint4 v[8];
#pragma unroll
        for (int j = 0; j < 8; j++) s[j] = __ldg(&g_col[e + j]);
#pragma unroll
        for (int j = 0; j < 8; j++) v[j] = T[(size_t)s[j] * 16 + sub];
#pragma unroll
        for (int j = 0; j < 8; j++) {
            const __half2* p = (const __half2*)&v[j];
#pragma unroll
            for (int q = 0; q < 4; q++) {
                float2 f = __half22float2(p[q]);
                acc[q * 2] += f.x; acc[q * 2 + 1] += f.y;
            }
        }
    }
    for (; e + 4 <= e1; e += 4) {
        int s[4];
        uint4 v[4];
#pragma unroll
        for (int j = 0; j < 4; j++) s[j] = __ldg(&g_col[e + j]);
#pragma unroll
        for (int j = 0; j < 4; j++) v[j] = T[(size_t)s[j] * 16 + sub];
#pragma unroll
        for (int j = 0; j < 4; j++) {
            const __half2* p = (const __half2*)&v[j];
#pragma unroll
            for (int q = 0; q < 4; q++) {
                float2 f = __half22float2(p[q]);
                acc[q * 2] += f.x; acc[q * 2 + 1] += f.y;
            }
        }
    }
    for (; e < e1; ++e) {
        int s = __ldg(&g_col[e]);
        uint4 v = T[(size_t)s * 16 + sub];
        const __half2* p = (const __half2*)&v;
#pragma unroll
        for (int q = 0; q < 4; q++) {
            float2 f = __half22float2(p[q]);
            acc[q * 2] += f.x; acc[q * 2 + 1] += f.y;
        }
    }

    float4 be0 = ((const float4*)beta)[sub * 2];
    float4 be1v = ((const float4*)beta)[sub * 2 + 1];
    float y[8];
    y[0] = fmaxf(0.f, fmaf(di, acc[0], be0.x));
    y[1] = fmaxf(0.f, fmaf(di, acc[1], be0.y));
    y[2] = fmaxf(0.f, fmaf(di, acc[2], be0.z));
    y[3] = fmaxf(0.f, fmaf(di, acc[3], be0.w));
    y[4] = fmaxf(0.f, fmaf(di, acc[4], be1v.x));
    y[5] = fmaxf(0.f, fmaf(di, acc[5], be1v.y));
    y[6] = fmaxf(0.f, fmaf(di, acc[6], be1v.z));
    y[7] = fmaxf(0.f, fmaf(di, acc[7], be1v.w));

    if (!FINAL) {
        uint4 o;
        __half2* p = (__half2*)&o;
        p[0] = __floats2half2_rn(y[0], y[1]);
        p[1] = __floats2half2_rn(y[2], y[3]);
        p[2] = __floats2half2_rn(y[4], y[5]);
        p[3] = __floats2half2_rn(y[6], y[7]);
        ((uint4*)g_h)[(size_t)node * 16 + sub] = o;
    } else {
        float4 wl0 = ((const float4*)Wl)[sub * 2];
        float4 wl1 = ((const float4*)Wl)[sub * 2 + 1];
        float s = y[0] * wl0.x + y[1] * wl0.y + y[2] * wl0.z + y[3] * wl0.w +
                  y[4] * wl1.x + y[5] * wl1.y + y[6] * wl1.z + y[7] * wl1.w;
        unsigned mask = half ? 0xFFFF0000u : 0x0000FFFFu;
#pragma unroll
        for (int off = 8; off > 0; off >>= 1)
            s += __shfl_xor_sync(mask, s, off);
        if (sub == 0) atomicAdd(&g_gsum[batch[node]], s);
    }
}

__global__ void k_final(float* __restrict__ out, const float* __restrict__ bl) {
    int g = blockIdx.x * blockDim.x + threadIdx.x;
    if (g < GG) out[g] = g_gsum[g] / fmaxf((float)g_gcnt[g], 1.0f) + bl[0];
}

// ---------------- host launcher --------------------------------------------
extern "C" void kernel_launch(void* const* d_in, const int* in_sizes, int n_in,
                              void* d_out, int out_size) {
    const float* x     = (const float*)d_in[0];
    const int*   ei    = (const int*)d_in[1];
    const int*   batch = (const int*)d_in[2];
    const float* W1 = (const float*)d_in[3];
    const float* b1 = (const float*)d_in[4];
    const float* g1 = (const float*)d_in[5];
    const float* be1 = (const float*)d_in[6];
    const float* m1 = (const float*)d_in[7];
    const float* v1 = (const float*)d_in[8];
    const float* W2 = (const float*)d_in[9];
    const float* b2 = (const float*)d_in[10];
    const float* g2 = (const float*)d_in[11];
    const float* be2 = (const float*)d_in[12];
    const float* m2 = (const float*)d_in[13];
    const float* v2 = (const float*)d_in[14];
    const float* W3 = (const float*)d_in[15];
    const float* b3 = (const float*)d_in[16];
    const float* g3 = (const float*)d_in[17];
    const float* be3 = (const float*)d_in[18];
    const float* m3 = (const float*)d_in[19];
    const float* v3 = (const float*)d_in[20];
    const float* Wl = (const float*)d_in[21];
    const float* bl = (const float*)d_in[22];

    __half *t, *h, *Wh;
    float *beta;
    cudaGetSymbolAddress((void**)&t, g_t);
    cudaGetSymbolAddress((void**)&h, g_h);
    cudaGetSymbolAddress((void**)&Wh, g_Wh);
    cudaGetSymbolAddress((void**)&beta, g_beta);

    const int GEMM_SMEM = 2 * 128 * 136 * (int)sizeof(__half);   // 69632
    cudaFuncSetAttribute(k_gemm_tc<true>,  cudaFuncAttributeMaxDynamicSharedMemorySize, GEMM_SMEM);
    cudaFuncSetAttribute(k_gemm_tc<false>, cudaFuncAttributeMaxDynamicSharedMemorySize, GEMM_SMEM);

    static cudaStream_t s1 = nullptr;
    static cudaEvent_t evStart = nullptr, evHist = nullptr, evG1 = nullptr;
    if (s1 == nullptr) {
        cudaStreamCreateWithFlags(&s1, cudaStreamNonBlocking);
        cudaEventCreateWithFlags(&evStart, cudaEventDisableTiming);
        cudaEventCreateWithFlags(&evHist, cudaEventDisableTiming);
        cudaEventCreateWithFlags(&evG1, cudaEventDisableTiming);
    }

    const int TPB = 256;
    const int GEMM_BLOCKS = (NN + 127) / 128;                    // 782
    const int AGG_BLOCKS = ((NN + 1) / 2 * 32 + TPB - 1) / TPB;  // 6250

    // ---- fork: side stream handles weight prep (input-only dependency)
    cudaEventRecord(evStart, 0);
    cudaStreamWaitEvent(s1, evStart, 0);
    {
        dim3 grid(64, 3);
        k_prep_w<<<grid, 256, 0, s1>>>(W1, W2, W3, b1, b2, b3, g1, g2, g3,
                                       be1, be2, be3, m1, m2, m3, v1, v2, v3);
    }

    // ---- main stream: graph preprocessing
    k_zero<<<(NN + TPB - 1) / TPB, TPB>>>();
    k_hist<<<(EE + TPB - 1) / TPB, TPB>>>(ei, batch);
    cudaEventRecord(evHist, 0);                         // gemm1 needs only g_deg
    k_scan_local<<<NB, SCAN_B>>>();                     // produces dinv + scan
    k_scan_part<<<1, 128>>>();
    k_scan_add<<<(NN + TPB) / TPB, TPB>>>();
    k_fill<<<(EE + TPB - 1) / TPB, TPB>>>(ei);

    // ---- side stream: gemm1 (needs Wh + deg), overlaps the whole scan chain
    cudaStreamWaitEvent(s1, evHist, 0);
    k_gemm_tc<true><<<GEMM_BLOCKS, 256, GEMM_SMEM, s1>>>(x, Wh, t);
    cudaEventRecord(evG1, s1);

    // ---- join, then layers (serial on main stream)
    cudaStreamWaitEvent(0, evG1, 0);
    k_agg16<false><<<AGG_BLOCKS, TPB>>>(beta, nullptr, nullptr);
    k_gemm_tc<false><<<GEMM_BLOCKS, 256, GEMM_SMEM>>>(h, Wh + HH * HH, t);
    k_agg16<false><<<AGG_BLOCKS, TPB>>>(beta + HH, nullptr, nullptr);
    k_gemm_tc<false><<<GEMM_BLOCKS, 256, GEMM_SMEM>>>(h, Wh + 2 * HH * HH, t);
    k_agg16<true><<<AGG_BLOCKS, TPB>>>(beta + 2 * HH, Wl, batch);

    k_final<<<(GG + TPB - 1) / TPB, TPB>>>((float*)d_out, bl);
}